// round 14
// baseline (speedup 1.0000x reference)
#include <cuda_runtime.h>
#include <cstdint>

#define DINL __device__ __forceinline__

namespace i8g {

constexpr int SD = 8192, KD = 4096, ND = 4096;
constexpr int BM = 64, BN = 128, BK = 128;      // CTA tile; BK in int8 elements
constexpr int STAGES = 4;
constexpr int NCHUNK = KD / BK;                 // 32
constexpr int THREADS = 256;                    // wids 0-3: IMMA (cols 0-47); wids 4-7: dp4a (cols 48-127)

constexpr int A_STAGE = BM * BK;                // 8 KB
constexpr int B_STAGE = BN * BK;                // 16 KB
constexpr uint32_t OFF_A = 0;
constexpr uint32_t OFF_B = STAGES * A_STAGE;    // 32 KB
constexpr uint32_t SMEM_BYTES = OFF_B + STAGES * B_STAGE + 1024;  // ~97 KB

__device__ __align__(16) int8_t g_xq[(size_t)SD * KD];   // 32 MB
__device__ __align__(16) int8_t g_wq[(size_t)ND * KD];   // 16 MB

DINL uint32_t smem_u32(const void* p) {
  uint32_t a;
  asm("{ .reg .u64 t; cvta.to.shared.u64 t, %1; cvt.u32.u64 %0, t; }" : "=r"(a) : "l"(p));
  return a;
}
DINL uint32_t swz(uint32_t o) { return o ^ ((o >> 3) & 0x70); }   // SW128
DINL void cp16(uint32_t d, const void* s) {
  asm volatile("cp.async.cg.shared.global [%0], [%1], 16;" :: "r"(d), "l"(s) : "memory");
}
DINL void cp_commit() { asm volatile("cp.async.commit_group;" ::: "memory"); }
DINL void cp_wait2()  { asm volatile("cp.async.wait_group 2;" ::: "memory"); }

DINL void ldm4(uint32_t* r, uint32_t addr) {
  asm volatile("ldmatrix.sync.aligned.m8n8.x4.shared.b16 {%0,%1,%2,%3}, [%4];"
               : "=r"(r[0]), "=r"(r[1]), "=r"(r[2]), "=r"(r[3]) : "r"(addr));
}
DINL void ldm2(uint32_t* r, uint32_t addr) {
  asm volatile("ldmatrix.sync.aligned.m8n8.x2.shared.b16 {%0,%1}, [%2];"
               : "=r"(r[0]), "=r"(r[1]) : "r"(addr));
}
DINL void mma_s8(int* d, const uint32_t* a, const uint32_t* b) {
  asm volatile(
      "mma.sync.aligned.m16n8k32.row.col.s32.s8.s8.s32 "
      "{%0,%1,%2,%3}, {%4,%5,%6,%7}, {%8,%9}, {%0,%1,%2,%3};"
      : "+r"(d[0]), "+r"(d[1]), "+r"(d[2]), "+r"(d[3])
      : "r"(a[0]), "r"(a[1]), "r"(a[2]), "r"(a[3]), "r"(b[0]), "r"(b[1]));
}
DINL int4 lds128(uint32_t addr) {
  int4 v;
  asm volatile("ld.shared.v4.b32 {%0,%1,%2,%3}, [%4];"
               : "=r"(v.x), "=r"(v.y), "=r"(v.z), "=r"(v.w) : "r"(addr));
  return v;
}

DINL int cvt_word(uint32_t u) {
  const int iv = (int)u;
  if (iv >= -128 && iv <= 127) return iv;
  return __float2int_rn(__uint_as_float(u));
}
DINL uint32_t pack4(uint4 v) {
  const int a = cvt_word(v.x), b = cvt_word(v.y), c = cvt_word(v.z), d = cvt_word(v.w);
  return (uint32_t)(a & 0xff) | ((uint32_t)(b & 0xff) << 8) |
         ((uint32_t)(c & 0xff) << 16) | ((uint32_t)(d & 0xff) << 24);
}

constexpr int NX16 = (SD * KD) / 16;
constexpr int NW16 = (ND * KD) / 16;

__global__ void __launch_bounds__(256)
pack_all_kernel(const uint4* __restrict__ xsrc, const uint4* __restrict__ wsrc)
{
  const int idx = blockIdx.x * blockDim.x + threadIdx.x;
  const uint4* s;
  uint4* dst;
  int o;
  if (idx < NX16) { s = xsrc + (size_t)idx * 4; dst = (uint4*)g_xq; o = idx; }
  else if (idx < NX16 + NW16) { s = wsrc + (size_t)(idx - NX16) * 4; dst = (uint4*)g_wq; o = idx - NX16; }
  else return;
  uint4 v;
  v.x = pack4(s[0]); v.y = pack4(s[1]); v.z = pack4(s[2]); v.w = pack4(s[3]);
  dst[o] = v;
}

__global__ void __launch_bounds__(THREADS, 2)
i8gemm_kernel(const float* __restrict__ sxp, const float* __restrict__ swp,
              const float* __restrict__ syp, float* __restrict__ out)
{
  extern __shared__ char smraw[];
  const uint32_t sraw = smem_u32(smraw);
  const uint32_t base = (sraw + 1023u) & ~1023u;

  const int tid  = threadIdx.x;
  const int wid  = tid >> 5;
  const int lane = tid & 31;
  const int m0 = blockIdx.y * BM;
  const int n0 = blockIdx.x * BN;

  const uint32_t abase = base + OFF_A;
  const uint32_t bbase = base + OFF_B;
  const int8_t* __restrict__ x = g_xq;
  const int8_t* __restrict__ w = g_wq;

  auto load_chunk = [&](int kc, int st) {
    const int8_t* ga = x + (size_t)m0 * KD + (size_t)kc * BK;
    const uint32_t sa = abase + st * A_STAGE;
    #pragma unroll
    for (int i = 0; i < (BM * BK / 16) / THREADS; i++) {   // 2
      int u = i * THREADS + tid;
      int r = u >> 3, c = (u & 7) << 4;
      cp16(sa + swz((uint32_t)((r << 7) + c)), ga + (size_t)r * KD + c);
    }
    const int8_t* gb = w + (size_t)n0 * KD + (size_t)kc * BK;
    const uint32_t sb = bbase + st * B_STAGE;
    #pragma unroll
    for (int i = 0; i < (BN * BK / 16) / THREADS; i++) {   // 4
      int u = i * THREADS + tid;
      int r = u >> 3, c = (u & 7) << 4;
      cp16(sb + swz((uint32_t)((r << 7) + c)), gb + (size_t)r * KD + c);
    }
  };

  #pragma unroll
  for (int s = 0; s < STAGES - 1; s++) { load_chunk(s, s); cp_commit(); }

  if (wid < 4) {
    // ==== IMMA half: cols [0,48), 2x2 warps, 32x24 tiles (identical to R11) ====
    const int warp_m = wid & 1;                        // rows warp_m*32
    const int warp_n = (wid >> 1) & 1;                 // cols warp_n*24

    int acc[2][3][4];
    #pragma unroll
    for (int i = 0; i < 2; i++)
      #pragma unroll
      for (int j = 0; j < 3; j++)
        #pragma unroll
        for (int k = 0; k < 4; k++) acc[i][j][k] = 0;

    const uint32_t a_row_l  = (uint32_t)(warp_m * 32 + (lane & 15));
    const uint32_t a_byt_l  = (uint32_t)((lane >> 4) << 4);
    const uint32_t b4_row_l = (uint32_t)(warp_n * 24 + (lane & 7) + ((lane & 16) ? 8 : 0));
    const uint32_t b2_row_l = (uint32_t)(warp_n * 24 + 16 + (lane & 7));
    const uint32_t b_byt_l  = (uint32_t)((lane & 8) ? 16 : 0);

    for (int kc = 0; kc < NCHUNK; kc++) {
      const int st = kc % STAGES;
      cp_wait2();
      __syncthreads();
      if (kc + STAGES - 1 < NCHUNK) load_chunk(kc + STAGES - 1, (kc + STAGES - 1) % STAGES);
      cp_commit();

      const uint32_t sa = abase + st * A_STAGE;
      const uint32_t sb = bbase + st * B_STAGE;

      #pragma unroll
      for (int ks = 0; ks < BK / 32; ks++) {
        uint32_t af[2][4];
        #pragma unroll
        for (int mt = 0; mt < 2; mt++)
          ldm4(af[mt], sa + swz(((a_row_l + mt * 16) << 7) + a_byt_l + ks * 32));
        uint32_t bf[6];
        ldm4(bf,     sb + swz((b4_row_l << 7) + b_byt_l + ks * 32));
        ldm2(bf + 4, sb + swz((b2_row_l << 7) + b_byt_l + ks * 32));
        #pragma unroll
        for (int mt = 0; mt < 2; mt++)
          #pragma unroll
          for (int nt = 0; nt < 3; nt++)
            mma_s8(acc[mt][nt], af[mt], &bf[nt * 2]);
      }
    }

    // epilogue (cols 0..47)
    const int qr = lane >> 2, qc = lane & 3;
    #pragma unroll
    for (int mt = 0; mt < 2; mt++) {
      const int r0 = warp_m * 32 + mt * 16 + qr;
      const int r1 = r0 + 8;
      const float rxy0 = __fdiv_rn(sxp[m0 + r0], syp[m0 + r0]);
      const float rxy1 = __fdiv_rn(sxp[m0 + r1], syp[m0 + r1]);
      float* o0 = out + (size_t)(m0 + r0) * ND + n0;
      float* o1 = out + (size_t)(m0 + r1) * ND + n0;
      #pragma unroll
      for (int nt = 0; nt < 3; nt++) {
        const int c0 = warp_n * 24 + nt * 8 + 2 * qc;
        const float sw0 = swp[n0 + c0], sw1 = swp[n0 + c0 + 1];
        const int* d = acc[mt][nt];
        const float s00 = __fmul_rn(rxy0, sw0), s01 = __fmul_rn(rxy0, sw1);
        const float s10 = __fmul_rn(rxy1, sw0), s11 = __fmul_rn(rxy1, sw1);
        int q00 = __float2int_rn(__fmul_rn(__int2float_rn(d[0]), s00));
        int q01 = __float2int_rn(__fmul_rn(__int2float_rn(d[1]), s01));
        int q10 = __float2int_rn(__fmul_rn(__int2float_rn(d[2]), s10));
        int q11 = __float2int_rn(__fmul_rn(__int2float_rn(d[3]), s11));
        q00 = q00 < -128 ? -128 : (q00 > 127 ? 127 : q00);
        q01 = q01 < -128 ? -128 : (q01 > 127 ? 127 : q01);
        q10 = q10 < -128 ? -128 : (q10 > 127 ? 127 : q10);
        q11 = q11 < -128 ? -128 : (q11 > 127 ? 127 : q11);
        *(float2*)(o0 + c0) = make_float2((float)q00, (float)q01);
        *(float2*)(o1 + c0) = make_float2((float)q10, (float)q11);
      }
    }
  } else {
    // ==== dp4a half: cols [48,128), 4x10 blocking — SPILL-FREE rewrite ====
    // Per-iteration live set: dacc 40 + a 16 + b 8 + addressing ~12  (<80 regs)
    const int dw = wid - 4;              // 0..3
    const int tx = lane & 7;             // col group: cols 48 + tx + 8j, j 0..9
    const int ry = lane >> 3;            // 0..3
    const int rowbase = dw * 4 + ry;     // rows rowbase + 16i, i 0..3
    const uint32_t xra = (uint32_t)(rowbase & 7) << 4;
    const uint32_t xrb = (uint32_t)tx << 4;                 // (48+tx)%8 == tx
    const uint32_t aoff = (uint32_t)rowbase << 7;
    const uint32_t boff = (uint32_t)(48 + tx) << 7;

    int dacc[4][10];
    #pragma unroll
    for (int i = 0; i < 4; i++)
      #pragma unroll
      for (int j = 0; j < 10; j++) dacc[i][j] = 0;

    for (int kc = 0; kc < NCHUNK; kc++) {
      const int st = kc % STAGES;
      cp_wait2();
      __syncthreads();
      if (kc + STAGES - 1 < NCHUNK) load_chunk(kc + STAGES - 1, (kc + STAGES - 1) % STAGES);
      cp_commit();

      const uint32_t sa = abase + st * A_STAGE;
      const uint32_t sb = bbase + st * B_STAGE;

      #pragma unroll 1
      for (int kk4 = 0; kk4 < BK / 16; kk4++) {             // 8 iters, 4 k-words each
        const uint32_t ka = sa + aoff + (((uint32_t)kk4 << 4) ^ xra);
        const uint32_t kb = sb + boff + (((uint32_t)kk4 << 4) ^ xrb);
        int4 a0 = lds128(ka);
        int4 a1 = lds128(ka + 2048);
        int4 a2 = lds128(ka + 4096);
        int4 a3 = lds128(ka + 6144);
        #pragma unroll
        for (int jp = 0; jp < 5; jp++) {                    // B cols in pairs: 8 live regs
          int4 b0 = lds128(kb + (2 * jp) * 1024);
          int4 b1 = lds128(kb + (2 * jp + 1) * 1024);
          int* c0 = &dacc[0][2 * jp]; int* c1 = &dacc[0][2 * jp + 1];
          int* c2 = &dacc[1][2 * jp]; int* c3 = &dacc[1][2 * jp + 1];
          int* c4 = &dacc[2][2 * jp]; int* c5 = &dacc[2][2 * jp + 1];
          int* c6 = &dacc[3][2 * jp]; int* c7 = &dacc[3][2 * jp + 1];
          *c0 = __dp4a(a0.x, b0.x, *c0); *c0 = __dp4a(a0.y, b0.y, *c0);
          *c0 = __dp4a(a0.z, b0.z, *c0); *c0 = __dp4a(a0.w, b0.w, *c0);
          *c1 = __dp4a(a0.x, b1.x, *c1); *c1 = __dp4a(a0.y, b1.y, *c1);
          *c1 = __dp4a(a0.z, b1.z, *c1); *c1 = __dp4a(a0.w, b1.w, *c1);
          *c2 = __dp4a(a1.x, b0.x, *c2); *c2 = __dp4a(a1.y, b0.y, *c2);
          *c2 = __dp4a(a1.z, b0.z, *c2); *c2 = __dp4a(a1.w, b0.w, *c2);
          *c3 = __dp4a(a1.x, b1.x, *c3); *c3 = __dp4a(a1.y, b1.y, *c3);
          *c3 = __dp4a(a1.z, b1.z, *c3); *c3 = __dp4a(a1.w, b1.w, *c3);
          *c4 = __dp4a(a2.x, b0.x, *c4); *c4 = __dp4a(a2.y, b0.y, *c4);
          *c4 = __dp4a(a2.z, b0.z, *c4); *c4 = __dp4a(a2.w, b0.w, *c4);
          *c5 = __dp4a(a2.x, b1.x, *c5); *c5 = __dp4a(a2.y, b1.y, *c5);
          *c5 = __dp4a(a2.z, b1.z, *c5); *c5 = __dp4a(a2.w, b1.w, *c5);
          *c6 = __dp4a(a3.x, b0.x, *c6); *c6 = __dp4a(a3.y, b0.y, *c6);
          *c6 = __dp4a(a3.z, b0.z, *c6); *c6 = __dp4a(a3.w, b0.w, *c6);
          *c7 = __dp4a(a3.x, b1.x, *c7); *c7 = __dp4a(a3.y, b1.y, *c7);
          *c7 = __dp4a(a3.z, b1.z, *c7); *c7 = __dp4a(a3.w, b1.w, *c7);
        }
      }
    }

    // epilogue (cols 48..127)
    #pragma unroll
    for (int i = 0; i < 4; i++) {
      const int r = m0 + rowbase + 16 * i;
      const float rxy = __fdiv_rn(sxp[r], syp[r]);
      float* o = out + (size_t)r * ND;
      #pragma unroll
      for (int j = 0; j < 10; j++) {
        const int c = n0 + 48 + tx + 8 * j;
        const float s = __fmul_rn(rxy, swp[c]);
        const float f = __fmul_rn(__int2float_rn(dacc[i][j]), s);
        int q = __float2int_rn(f);
        q = q < -128 ? -128 : (q > 127 ? 127 : q);
        o[c] = (float)q;
      }
    }
  }
}

} // namespace i8g

extern "C" void kernel_launch(void* const* d_in, const int* in_sizes, int n_in,
                              void* d_out, int out_size) {
  using namespace i8g;

  const void* x = nullptr; const void* w = nullptr;
  const float *sx = nullptr, *sw = nullptr, *sy = nullptr;
  for (int i = 0; i < n_in; i++) {
    const long long n = (long long)in_sizes[i];
    if (n == (long long)SD * KD)       x = d_in[i];
    else if (n == (long long)ND * KD)  w = d_in[i];
    else if (n == ND)                  sw = (const float*)d_in[i];
    else if (n == SD) { if (!sx) sx = (const float*)d_in[i]; else sy = (const float*)d_in[i]; }
  }
  if (!x || !w || !sx || !sw || !sy) return;

  float* out = (float*)d_out;

  {
    const int total = NX16 + NW16;
    pack_all_kernel<<<(total + 255) / 256, 256>>>((const uint4*)x, (const uint4*)w);
  }

  cudaFuncSetAttribute(i8gemm_kernel, cudaFuncAttributeMaxDynamicSharedMemorySize,
                       (int)SMEM_BYTES);
  dim3 grid(ND / BN, SD / BM);   // (32, 128)
  i8gemm_kernel<<<grid, THREADS, SMEM_BYTES>>>(sx, sw, sy, out);

  const size_t SN = (size_t)SD * (size_t)ND;
  if ((size_t)out_size > SN) {
    cudaMemcpyAsync((float*)d_out + SN, sy,
                    ((size_t)out_size - SN) * sizeof(float),
                    cudaMemcpyDeviceToDevice);
  }
}

// round 15
// speedup vs baseline: 1.0398x; 1.0398x over previous
#include <cuda_runtime.h>
#include <cstdint>

#define DINL __device__ __forceinline__

namespace i8g {

constexpr int SD = 8192, KD = 4096, ND = 4096;
constexpr int BM = 64, BN = 128, BK = 128;      // CTA tile; BK in int8 elements
constexpr int STAGES = 4;
constexpr int NCHUNK = KD / BK;                 // 32
constexpr int THREADS = 512;                    // wids 0-7: IMMA (cols 0-63); wids 8-15: dp4a (cols 64-127)

constexpr int A_STAGE = BM * BK;                // 8 KB
constexpr int B_STAGE = BN * BK;                // 16 KB
constexpr uint32_t OFF_A = 0;
constexpr uint32_t OFF_B = STAGES * A_STAGE;    // 32 KB
constexpr uint32_t SMEM_BYTES = OFF_B + STAGES * B_STAGE + 1024;  // ~97 KB

__device__ __align__(16) int8_t g_xq[(size_t)SD * KD];   // 32 MB
__device__ __align__(16) int8_t g_wq[(size_t)ND * KD];   // 16 MB

DINL uint32_t smem_u32(const void* p) {
  uint32_t a;
  asm("{ .reg .u64 t; cvta.to.shared.u64 t, %1; cvt.u32.u64 %0, t; }" : "=r"(a) : "l"(p));
  return a;
}
DINL uint32_t swz(uint32_t o) { return o ^ ((o >> 3) & 0x70); }   // SW128
DINL void cp16(uint32_t d, const void* s) {
  asm volatile("cp.async.cg.shared.global [%0], [%1], 16;" :: "r"(d), "l"(s) : "memory");
}
DINL void cp_commit() { asm volatile("cp.async.commit_group;" ::: "memory"); }
DINL void cp_wait2()  { asm volatile("cp.async.wait_group 2;" ::: "memory"); }

DINL void ldm4(uint32_t* r, uint32_t addr) {
  asm volatile("ldmatrix.sync.aligned.m8n8.x4.shared.b16 {%0,%1,%2,%3}, [%4];"
               : "=r"(r[0]), "=r"(r[1]), "=r"(r[2]), "=r"(r[3]) : "r"(addr));
}
DINL void mma_s8(int* d, const uint32_t* a, const uint32_t* b) {
  asm volatile(
      "mma.sync.aligned.m16n8k32.row.col.s32.s8.s8.s32 "
      "{%0,%1,%2,%3}, {%4,%5,%6,%7}, {%8,%9}, {%0,%1,%2,%3};"
      : "+r"(d[0]), "+r"(d[1]), "+r"(d[2]), "+r"(d[3])
      : "r"(a[0]), "r"(a[1]), "r"(a[2]), "r"(a[3]), "r"(b[0]), "r"(b[1]));
}
DINL int4 lds128(uint32_t addr) {
  int4 v;
  asm volatile("ld.shared.v4.b32 {%0,%1,%2,%3}, [%4];"
               : "=r"(v.x), "=r"(v.y), "=r"(v.z), "=r"(v.w) : "r"(addr));
  return v;
}

DINL int cvt_word(uint32_t u) {
  const int iv = (int)u;
  if (iv >= -128 && iv <= 127) return iv;
  return __float2int_rn(__uint_as_float(u));
}
DINL uint32_t pack4(uint4 v) {
  const int a = cvt_word(v.x), b = cvt_word(v.y), c = cvt_word(v.z), d = cvt_word(v.w);
  return (uint32_t)(a & 0xff) | ((uint32_t)(b & 0xff) << 8) |
         ((uint32_t)(c & 0xff) << 16) | ((uint32_t)(d & 0xff) << 24);
}

constexpr int NX16 = (SD * KD) / 16;
constexpr int NW16 = (ND * KD) / 16;

__global__ void __launch_bounds__(256)
pack_all_kernel(const uint4* __restrict__ xsrc, const uint4* __restrict__ wsrc)
{
  const int idx = blockIdx.x * blockDim.x + threadIdx.x;
  const uint4* s;
  uint4* dst;
  int o;
  if (idx < NX16) { s = xsrc + (size_t)idx * 4; dst = (uint4*)g_xq; o = idx; }
  else if (idx < NX16 + NW16) { s = wsrc + (size_t)(idx - NX16) * 4; dst = (uint4*)g_wq; o = idx - NX16; }
  else return;
  uint4 v;
  v.x = pack4(s[0]); v.y = pack4(s[1]); v.z = pack4(s[2]); v.w = pack4(s[3]);
  dst[o] = v;
}

__global__ void __launch_bounds__(THREADS, 2)
i8gemm_kernel(const float* __restrict__ sxp, const float* __restrict__ swp,
              const float* __restrict__ syp, float* __restrict__ out)
{
  extern __shared__ char smraw[];
  const uint32_t sraw = smem_u32(smraw);
  const uint32_t base = (sraw + 1023u) & ~1023u;

  const int tid  = threadIdx.x;
  const int wid  = tid >> 5;
  const int lane = tid & 31;
  const int m0 = blockIdx.y * BM;
  const int n0 = blockIdx.x * BN;

  const uint32_t abase = base + OFF_A;
  const uint32_t bbase = base + OFF_B;
  const int8_t* __restrict__ x = g_xq;
  const int8_t* __restrict__ w = g_wq;

  // producer: A 1 cp16/thread, B 2 cp16/thread
  auto load_chunk = [&](int kc, int st) {
    const int8_t* ga = x + (size_t)m0 * KD + (size_t)kc * BK;
    const uint32_t sa = abase + st * A_STAGE;
    {
      int u = tid;                           // 512 = 64 rows * 8 chunks
      int r = u >> 3, c = (u & 7) << 4;
      cp16(sa + swz((uint32_t)((r << 7) + c)), ga + (size_t)r * KD + c);
    }
    const int8_t* gb = w + (size_t)n0 * KD + (size_t)kc * BK;
    const uint32_t sb = bbase + st * B_STAGE;
    #pragma unroll
    for (int i = 0; i < 2; i++) {
      int u = i * THREADS + tid;
      int r = u >> 3, c = (u & 7) << 4;
      cp16(sb + swz((uint32_t)((r << 7) + c)), gb + (size_t)r * KD + c);
    }
  };

  #pragma unroll
  for (int s = 0; s < STAGES - 1; s++) { load_chunk(s, s); cp_commit(); }

  if (wid < 8) {
    // ==== IMMA half: cols [0,64), 2m x 4n warps, warp tile 32x16 ====
    const int warp_m = wid & 1;                        // rows warp_m*32
    const int warp_n = wid >> 1;                       // cols warp_n*16 (0..3)

    int acc[2][2][4];
    #pragma unroll
    for (int i = 0; i < 2; i++)
      #pragma unroll
      for (int j = 0; j < 2; j++)
        #pragma unroll
        for (int k = 0; k < 4; k++) acc[i][j][k] = 0;

    const uint32_t a_row_l = (uint32_t)(warp_m * 32 + (lane & 15));
    const uint32_t a_byt_l = (uint32_t)((lane >> 4) << 4);
    const uint32_t b_row_l = (uint32_t)(warp_n * 16 + (lane & 7) + ((lane & 16) ? 8 : 0));
    const uint32_t b_byt_l = (uint32_t)((lane & 8) ? 16 : 0);

    for (int kc = 0; kc < NCHUNK; kc++) {
      const int st = kc % STAGES;
      cp_wait2();
      __syncthreads();
      if (kc + STAGES - 1 < NCHUNK) load_chunk(kc + STAGES - 1, (kc + STAGES - 1) % STAGES);
      cp_commit();

      const uint32_t sa = abase + st * A_STAGE;
      const uint32_t sb = bbase + st * B_STAGE;

      #pragma unroll
      for (int ks = 0; ks < BK / 32; ks++) {
        uint32_t af[2][4];
        #pragma unroll
        for (int mt = 0; mt < 2; mt++)
          ldm4(af[mt], sa + swz(((a_row_l + mt * 16) << 7) + a_byt_l + ks * 32));
        uint32_t bf[4];
        ldm4(bf, sb + swz((b_row_l << 7) + b_byt_l + ks * 32));
        #pragma unroll
        for (int mt = 0; mt < 2; mt++)
          #pragma unroll
          for (int nt = 0; nt < 2; nt++)
            mma_s8(acc[mt][nt], af[mt], &bf[nt * 2]);
      }
    }

    // epilogue (cols 0..63)
    const int qr = lane >> 2, qc = lane & 3;
    #pragma unroll
    for (int mt = 0; mt < 2; mt++) {
      const int r0 = warp_m * 32 + mt * 16 + qr;
      const int r1 = r0 + 8;
      const float rxy0 = __fdiv_rn(sxp[m0 + r0], syp[m0 + r0]);
      const float rxy1 = __fdiv_rn(sxp[m0 + r1], syp[m0 + r1]);
      float* o0 = out + (size_t)(m0 + r0) * ND + n0;
      float* o1 = out + (size_t)(m0 + r1) * ND + n0;
      #pragma unroll
      for (int nt = 0; nt < 2; nt++) {
        const int c0 = warp_n * 16 + nt * 8 + 2 * qc;
        const float sw0 = swp[n0 + c0], sw1 = swp[n0 + c0 + 1];
        const int* d = acc[mt][nt];
        const float s00 = __fmul_rn(rxy0, sw0), s01 = __fmul_rn(rxy0, sw1);
        const float s10 = __fmul_rn(rxy1, sw0), s11 = __fmul_rn(rxy1, sw1);
        int q00 = __float2int_rn(__fmul_rn(__int2float_rn(d[0]), s00));
        int q01 = __float2int_rn(__fmul_rn(__int2float_rn(d[1]), s01));
        int q10 = __float2int_rn(__fmul_rn(__int2float_rn(d[2]), s10));
        int q11 = __float2int_rn(__fmul_rn(__int2float_rn(d[3]), s11));
        q00 = q00 < -128 ? -128 : (q00 > 127 ? 127 : q00);
        q01 = q01 < -128 ? -128 : (q01 > 127 ? 127 : q01);
        q10 = q10 < -128 ? -128 : (q10 > 127 ? 127 : q10);
        q11 = q11 < -128 ? -128 : (q11 > 127 ? 127 : q11);
        *(float2*)(o0 + c0) = make_float2((float)q00, (float)q01);
        *(float2*)(o1 + c0) = make_float2((float)q10, (float)q11);
      }
    }
  } else {
    // ==== dp4a half: cols [64,128), 8 warps, 2x8 blocking ====
    const int dw = wid - 8;              // 0..7
    const int tx = lane & 7;             // col: 64 + tx + 8j, j 0..7
    const int ry = lane >> 3;            // 0..3
    const int rowbase = dw * 4 + ry;     // 0..31; rows rowbase + 32i, i 0..1
    const uint32_t xra = (uint32_t)(rowbase & 7) << 4;
    const uint32_t xrb = (uint32_t)tx << 4;                 // (64+tx)%8 == tx
    const uint32_t aoff = (uint32_t)rowbase << 7;           // + i*4096
    const uint32_t boff = (uint32_t)(64 + tx) << 7;         // + j*1024

    int dacc[2][8];
    #pragma unroll
    for (int i = 0; i < 2; i++)
      #pragma unroll
      for (int j = 0; j < 8; j++) dacc[i][j] = 0;

    for (int kc = 0; kc < NCHUNK; kc++) {
      const int st = kc % STAGES;
      cp_wait2();
      __syncthreads();
      if (kc + STAGES - 1 < NCHUNK) load_chunk(kc + STAGES - 1, (kc + STAGES - 1) % STAGES);
      cp_commit();

      const uint32_t sa = abase + st * A_STAGE;
      const uint32_t sb = bbase + st * B_STAGE;

      #pragma unroll 1
      for (int kk4 = 0; kk4 < BK / 16; kk4++) {             // 8 iters, 4 k-words each
        const uint32_t ka = sa + aoff + (((uint32_t)kk4 << 4) ^ xra);
        const uint32_t kb = sb + boff + (((uint32_t)kk4 << 4) ^ xrb);
        int4 a0 = lds128(ka);
        int4 a1 = lds128(ka + 4096);
        #pragma unroll
        for (int jp = 0; jp < 4; jp++) {                    // B cols in pairs
          int4 b0 = lds128(kb + (2 * jp) * 1024);
          int4 b1 = lds128(kb + (2 * jp + 1) * 1024);
          int* c0 = &dacc[0][2 * jp]; int* c1 = &dacc[0][2 * jp + 1];
          int* c2 = &dacc[1][2 * jp]; int* c3 = &dacc[1][2 * jp + 1];
          *c0 = __dp4a(a0.x, b0.x, *c0); *c0 = __dp4a(a0.y, b0.y, *c0);
          *c0 = __dp4a(a0.z, b0.z, *c0); *c0 = __dp4a(a0.w, b0.w, *c0);
          *c1 = __dp4a(a0.x, b1.x, *c1); *c1 = __dp4a(a0.y, b1.y, *c1);
          *c1 = __dp4a(a0.z, b1.z, *c1); *c1 = __dp4a(a0.w, b1.w, *c1);
          *c2 = __dp4a(a1.x, b0.x, *c2); *c2 = __dp4a(a1.y, b0.y, *c2);
          *c2 = __dp4a(a1.z, b0.z, *c2); *c2 = __dp4a(a1.w, b0.w, *c2);
          *c3 = __dp4a(a1.x, b1.x, *c3); *c3 = __dp4a(a1.y, b1.y, *c3);
          *c3 = __dp4a(a1.z, b1.z, *c3); *c3 = __dp4a(a1.w, b1.w, *c3);
        }
      }
    }

    // epilogue (cols 64..127)
    #pragma unroll
    for (int i = 0; i < 2; i++) {
      const int r = m0 + rowbase + 32 * i;
      const float rxy = __fdiv_rn(sxp[r], syp[r]);
      float* o = out + (size_t)r * ND;
      #pragma unroll
      for (int j = 0; j < 8; j++) {
        const int c = n0 + 64 + tx + 8 * j;
        const float s = __fmul_rn(rxy, swp[c]);
        const float f = __fmul_rn(__int2float_rn(dacc[i][j]), s);
        int q = __float2int_rn(f);
        q = q < -128 ? -128 : (q > 127 ? 127 : q);
        o[c] = (float)q;
      }
    }
  }
}

} // namespace i8g

extern "C" void kernel_launch(void* const* d_in, const int* in_sizes, int n_in,
                              void* d_out, int out_size) {
  using namespace i8g;

  const void* x = nullptr; const void* w = nullptr;
  const float *sx = nullptr, *sw = nullptr, *sy = nullptr;
  for (int i = 0; i < n_in; i++) {
    const long long n = (long long)in_sizes[i];
    if (n == (long long)SD * KD)       x = d_in[i];
    else if (n == (long long)ND * KD)  w = d_in[i];
    else if (n == ND)                  sw = (const float*)d_in[i];
    else if (n == SD) { if (!sx) sx = (const float*)d_in[i]; else sy = (const float*)d_in[i]; }
  }
  if (!x || !w || !sx || !sw || !sy) return;

  float* out = (float*)d_out;

  {
    const int total = NX16 + NW16;
    pack_all_kernel<<<(total + 255) / 256, 256>>>((const uint4*)x, (const uint4*)w);
  }

  cudaFuncSetAttribute(i8gemm_kernel, cudaFuncAttributeMaxDynamicSharedMemorySize,
                       (int)SMEM_BYTES);
  dim3 grid(ND / BN, SD / BM);   // (32, 128)
  i8gemm_kernel<<<grid, THREADS, SMEM_BYTES>>>(sx, sw, sy, out);

  const size_t SN = (size_t)SD * (size_t)ND;
  if ((size_t)out_size > SN) {
    cudaMemcpyAsync((float*)d_out + SN, sy,
                    ((size_t)out_size - SN) * sizeof(float),
                    cudaMemcpyDeviceToDevice);
  }
}

// round 16
// speedup vs baseline: 1.1417x; 1.0980x over previous
#include <cuda_runtime.h>
#include <cstdint>

#define DINL __device__ __forceinline__

namespace i8g {

constexpr int SD = 8192, KD = 4096, ND = 4096;
constexpr int BM = 64, BN = 128, BK = 128;      // CTA tile; BK in int8 elements
constexpr int STAGES = 3;
constexpr int NCHUNK = KD / BK;                 // 32
constexpr int THREADS = 256;                    // wids 0-3: IMMA (cols 0-71); wids 4-7: dp4a (cols 72-127)

constexpr int A_STAGE = BM * BK;                // 8 KB
constexpr int B_STAGE = BN * BK;                // 16 KB
constexpr uint32_t OFF_A = 0;
constexpr uint32_t OFF_B = STAGES * A_STAGE;    // 24 KB
constexpr uint32_t SMEM_BYTES = OFF_B + STAGES * B_STAGE + 1024;  // ~74.8 KB -> 3 CTAs/SM

__device__ __align__(16) int8_t g_xq[(size_t)SD * KD];   // 32 MB
__device__ __align__(16) int8_t g_wq[(size_t)ND * KD];   // 16 MB

DINL uint32_t smem_u32(const void* p) {
  uint32_t a;
  asm("{ .reg .u64 t; cvta.to.shared.u64 t, %1; cvt.u32.u64 %0, t; }" : "=r"(a) : "l"(p));
  return a;
}
DINL uint32_t swz(uint32_t o) { return o ^ ((o >> 3) & 0x70); }   // SW128
DINL void cp16(uint32_t d, const void* s) {
  asm volatile("cp.async.cg.shared.global [%0], [%1], 16;" :: "r"(d), "l"(s) : "memory");
}
DINL void cp_commit() { asm volatile("cp.async.commit_group;" ::: "memory"); }
DINL void cp_wait1()  { asm volatile("cp.async.wait_group 1;" ::: "memory"); }

DINL void ldm4(uint32_t* r, uint32_t addr) {
  asm volatile("ldmatrix.sync.aligned.m8n8.x4.shared.b16 {%0,%1,%2,%3}, [%4];"
               : "=r"(r[0]), "=r"(r[1]), "=r"(r[2]), "=r"(r[3]) : "r"(addr));
}
DINL void ldm2(uint32_t* r, uint32_t addr) {
  asm volatile("ldmatrix.sync.aligned.m8n8.x2.shared.b16 {%0,%1}, [%2];"
               : "=r"(r[0]), "=r"(r[1]) : "r"(addr));
}
DINL void mma_s8(int* d, const uint32_t* a, const uint32_t* b) {
  asm volatile(
      "mma.sync.aligned.m16n8k32.row.col.s32.s8.s8.s32 "
      "{%0,%1,%2,%3}, {%4,%5,%6,%7}, {%8,%9}, {%0,%1,%2,%3};"
      : "+r"(d[0]), "+r"(d[1]), "+r"(d[2]), "+r"(d[3])
      : "r"(a[0]), "r"(a[1]), "r"(a[2]), "r"(a[3]), "r"(b[0]), "r"(b[1]));
}
DINL int4 lds128(uint32_t addr) {
  int4 v;
  asm volatile("ld.shared.v4.b32 {%0,%1,%2,%3}, [%4];"
               : "=r"(v.x), "=r"(v.y), "=r"(v.z), "=r"(v.w) : "r"(addr));
  return v;
}

DINL int cvt_word(uint32_t u) {
  const int iv = (int)u;
  if (iv >= -128 && iv <= 127) return iv;
  return __float2int_rn(__uint_as_float(u));
}
DINL uint32_t pack4(uint4 v) {
  const int a = cvt_word(v.x), b = cvt_word(v.y), c = cvt_word(v.z), d = cvt_word(v.w);
  return (uint32_t)(a & 0xff) | ((uint32_t)(b & 0xff) << 8) |
         ((uint32_t)(c & 0xff) << 16) | ((uint32_t)(d & 0xff) << 24);
}

constexpr int NX16 = (SD * KD) / 16;
constexpr int NW16 = (ND * KD) / 16;

__global__ void __launch_bounds__(256)
pack_all_kernel(const uint4* __restrict__ xsrc, const uint4* __restrict__ wsrc)
{
  const int idx = blockIdx.x * blockDim.x + threadIdx.x;
  const uint4* s;
  uint4* dst;
  int o;
  if (idx < NX16) { s = xsrc + (size_t)idx * 4; dst = (uint4*)g_xq; o = idx; }
  else if (idx < NX16 + NW16) { s = wsrc + (size_t)(idx - NX16) * 4; dst = (uint4*)g_wq; o = idx - NX16; }
  else return;
  uint4 v;
  v.x = pack4(s[0]); v.y = pack4(s[1]); v.z = pack4(s[2]); v.w = pack4(s[3]);
  dst[o] = v;
}

__global__ void __launch_bounds__(THREADS, 3)
i8gemm_kernel(const float* __restrict__ sxp, const float* __restrict__ swp,
              const float* __restrict__ syp, float* __restrict__ out)
{
  extern __shared__ char smraw[];
  const uint32_t sraw = smem_u32(smraw);
  const uint32_t base = (sraw + 1023u) & ~1023u;

  const int tid  = threadIdx.x;
  const int wid  = tid >> 5;
  const int lane = tid & 31;
  const int m0 = blockIdx.y * BM;
  const int n0 = blockIdx.x * BN;

  const uint32_t abase = base + OFF_A;
  const uint32_t bbase = base + OFF_B;
  const int8_t* __restrict__ x = g_xq;
  const int8_t* __restrict__ w = g_wq;

  auto load_chunk = [&](int kc, int st) {
    const int8_t* ga = x + (size_t)m0 * KD + (size_t)kc * BK;
    const uint32_t sa = abase + st * A_STAGE;
    #pragma unroll
    for (int i = 0; i < (BM * BK / 16) / THREADS; i++) {   // 2
      int u = i * THREADS + tid;
      int r = u >> 3, c = (u & 7) << 4;
      cp16(sa + swz((uint32_t)((r << 7) + c)), ga + (size_t)r * KD + c);
    }
    const int8_t* gb = w + (size_t)n0 * KD + (size_t)kc * BK;
    const uint32_t sb = bbase + st * B_STAGE;
    #pragma unroll
    for (int i = 0; i < (BN * BK / 16) / THREADS; i++) {   // 4
      int u = i * THREADS + tid;
      int r = u >> 3, c = (u & 7) << 4;
      cp16(sb + swz((uint32_t)((r << 7) + c)), gb + (size_t)r * KD + c);
    }
  };

  #pragma unroll
  for (int s = 0; s < STAGES - 1; s++) { load_chunk(s, s); cp_commit(); }

  if (wid < 4) {
    // ======= IMMA half: cols [0,72) — 4x1 warps, warp tile 16x72 (R12-proven) =======
    int acc[9][4];
    #pragma unroll
    for (int j = 0; j < 9; j++)
      #pragma unroll
      for (int k = 0; k < 4; k++) acc[j][k] = 0;

    const uint32_t a_row_l  = (uint32_t)(wid * 16 + (lane & 15));
    const uint32_t a_byt_l  = (uint32_t)((lane >> 4) << 4);
    const uint32_t b4_row_l = (uint32_t)((lane & 7) + ((lane & 16) ? 8 : 0));  // + 16*g4
    const uint32_t b2_row_l = (uint32_t)(64 + (lane & 7));
    const uint32_t b_byt_l  = (uint32_t)((lane & 8) ? 16 : 0);

    for (int kc = 0; kc < NCHUNK; kc++) {
      const int st = kc % STAGES;
      cp_wait1();
      __syncthreads();
      if (kc + STAGES - 1 < NCHUNK) load_chunk(kc + STAGES - 1, (kc + STAGES - 1) % STAGES);
      cp_commit();

      const uint32_t sa = abase + st * A_STAGE;
      const uint32_t sb = bbase + st * B_STAGE;

      #pragma unroll
      for (int ks = 0; ks < BK / 32; ks++) {
        uint32_t af[4];
        ldm4(af, sa + swz((a_row_l << 7) + a_byt_l + ks * 32));
        uint32_t bf4[4][4];
        #pragma unroll
        for (int g4 = 0; g4 < 4; g4++)
          ldm4(bf4[g4], sb + swz(((b4_row_l + 16 * g4) << 7) + b_byt_l + ks * 32));
        uint32_t bf2[2];
        ldm2(bf2, sb + swz((b2_row_l << 7) + b_byt_l + ks * 32));
        #pragma unroll
        for (int nt = 0; nt < 8; nt++)
          mma_s8(acc[nt], af, &bf4[nt >> 1][(nt & 1) * 2]);
        mma_s8(acc[8], af, bf2);
      }
    }

    // epilogue (cols 0..71, rows wid*16 + {qr, qr+8})
    const int qr = lane >> 2, qc = lane & 3;
    const int r0 = wid * 16 + qr;
    const int r1 = r0 + 8;
    const float rxy0 = __fdiv_rn(sxp[m0 + r0], syp[m0 + r0]);
    const float rxy1 = __fdiv_rn(sxp[m0 + r1], syp[m0 + r1]);
    float* o0 = out + (size_t)(m0 + r0) * ND + n0;
    float* o1 = out + (size_t)(m0 + r1) * ND + n0;
    #pragma unroll
    for (int nt = 0; nt < 9; nt++) {
      const int c0 = nt * 8 + 2 * qc;
      const float sw0 = swp[n0 + c0], sw1 = swp[n0 + c0 + 1];
      const int* d = acc[nt];
      const float s00 = __fmul_rn(rxy0, sw0), s01 = __fmul_rn(rxy0, sw1);
      const float s10 = __fmul_rn(rxy1, sw0), s11 = __fmul_rn(rxy1, sw1);
      int q00 = __float2int_rn(__fmul_rn(__int2float_rn(d[0]), s00));
      int q01 = __float2int_rn(__fmul_rn(__int2float_rn(d[1]), s01));
      int q10 = __float2int_rn(__fmul_rn(__int2float_rn(d[2]), s10));
      int q11 = __float2int_rn(__fmul_rn(__int2float_rn(d[3]), s11));
      q00 = q00 < -128 ? -128 : (q00 > 127 ? 127 : q00);
      q01 = q01 < -128 ? -128 : (q01 > 127 ? 127 : q01);
      q10 = q10 < -128 ? -128 : (q10 > 127 ? 127 : q10);
      q11 = q11 < -128 ? -128 : (q11 > 127 ? 127 : q11);
      *(float2*)(o0 + c0) = make_float2((float)q00, (float)q01);
      *(float2*)(o1 + c0) = make_float2((float)q10, (float)q11);
    }
  } else {
    // ======= dp4a half: cols [72,128) — 4 warps, 4x7 blocking, low liveness =======
    const int dw = wid - 4;              // 0..3
    const int tx = lane & 7;             // col group: cols 72 + tx + 8j, j 0..6
    const int ry = lane >> 3;            // 0..3
    const int rowbase = dw * 4 + ry;     // rows rowbase + 16i, i 0..3
    const uint32_t xra = (uint32_t)(rowbase & 7) << 4;
    const uint32_t xrb = (uint32_t)tx << 4;                 // (72+tx)%8 == tx
    const uint32_t aoff = (uint32_t)rowbase << 7;
    const uint32_t boff = (uint32_t)(72 + tx) << 7;

    int dacc[4][7];
    #pragma unroll
    for (int i = 0; i < 4; i++)
      #pragma unroll
      for (int j = 0; j < 7; j++) dacc[i][j] = 0;

    for (int kc = 0; kc < NCHUNK; kc++) {
      const int st = kc % STAGES;
      cp_wait1();
      __syncthreads();
      if (kc + STAGES - 1 < NCHUNK) load_chunk(kc + STAGES - 1, (kc + STAGES - 1) % STAGES);
      cp_commit();

      const uint32_t sa = abase + st * A_STAGE;
      const uint32_t sb = bbase + st * B_STAGE;

      #pragma unroll 1
      for (int kk4 = 0; kk4 < BK / 16; kk4++) {             // 8 iters, 4 k-words each
        const uint32_t ka = sa + aoff + (((uint32_t)kk4 << 4) ^ xra);
        const uint32_t kb = sb + boff + (((uint32_t)kk4 << 4) ^ xrb);
        int4 a0 = lds128(ka);
        int4 a1 = lds128(ka + 2048);
        int4 a2 = lds128(ka + 4096);
        int4 a3 = lds128(ka + 6144);
        #pragma unroll
        for (int jp = 0; jp < 3; jp++) {                    // cols j=2jp, 2jp+1 (pairs)
          int4 b0 = lds128(kb + (2 * jp) * 1024);
          int4 b1 = lds128(kb + (2 * jp + 1) * 1024);
          int* c0 = &dacc[0][2 * jp]; int* c1 = &dacc[0][2 * jp + 1];
          int* c2 = &dacc[1][2 * jp]; int* c3 = &dacc[1][2 * jp + 1];
          int* c4 = &dacc[2][2 * jp]; int* c5 = &dacc[2][2 * jp + 1];
          int* c6 = &dacc[3][2 * jp]; int* c7 = &dacc[3][2 * jp + 1];
          *c0 = __dp4a(a0.x, b0.x, *c0); *c0 = __dp4a(a0.y, b0.y, *c0);
          *c0 = __dp4a(a0.z, b0.z, *c0); *c0 = __dp4a(a0.w, b0.w, *c0);
          *c1 = __dp4a(a0.x, b1.x, *c1); *c1 = __dp4a(a0.y, b1.y, *c1);
          *c1 = __dp4a(a0.z, b1.z, *c1); *c1 = __dp4a(a0.w, b1.w, *c1);
          *c2 = __dp4a(a1.x, b0.x, *c2); *c2 = __dp4a(a1.y, b0.y, *c2);
          *c2 = __dp4a(a1.z, b0.z, *c2); *c2 = __dp4a(a1.w, b0.w, *c2);
          *c3 = __dp4a(a1.x, b1.x, *c3); *c3 = __dp4a(a1.y, b1.y, *c3);
          *c3 = __dp4a(a1.z, b1.z, *c3); *c3 = __dp4a(a1.w, b1.w, *c3);
          *c4 = __dp4a(a2.x, b0.x, *c4); *c4 = __dp4a(a2.y, b0.y, *c4);
          *c4 = __dp4a(a2.z, b0.z, *c4); *c4 = __dp4a(a2.w, b0.w, *c4);
          *c5 = __dp4a(a2.x, b1.x, *c5); *c5 = __dp4a(a2.y, b1.y, *c5);
          *c5 = __dp4a(a2.z, b1.z, *c5); *c5 = __dp4a(a2.w, b1.w, *c5);
          *c6 = __dp4a(a3.x, b0.x, *c6); *c6 = __dp4a(a3.y, b0.y, *c6);
          *c6 = __dp4a(a3.z, b0.z, *c6); *c6 = __dp4a(a3.w, b0.w, *c6);
          *c7 = __dp4a(a3.x, b1.x, *c7); *c7 = __dp4a(a3.y, b1.y, *c7);
          *c7 = __dp4a(a3.z, b1.z, *c7); *c7 = __dp4a(a3.w, b1.w, *c7);
        }
        {                                                    // col j=6 (single)
          int4 b0 = lds128(kb + 6 * 1024);
          int* c0 = &dacc[0][6]; int* c1 = &dacc[1][6];
          int* c2 = &dacc[2][6]; int* c3 = &dacc[3][6];
          *c0 = __dp4a(a0.x, b0.x, *c0); *c0 = __dp4a(a0.y, b0.y, *c0);
          *c0 = __dp4a(a0.z, b0.z, *c0); *c0 = __dp4a(a0.w, b0.w, *c0);
          *c1 = __dp4a(a1.x, b0.x, *c1); *c1 = __dp4a(a1.y, b0.y, *c1);
          *c1 = __dp4a(a1.z, b0.z, *c1); *c1 = __dp4a(a1.w, b0.w, *c1);
          *c2 = __dp4a(a2.x, b0.x, *c2); *c2 = __dp4a(a2.y, b0.y, *c2);
          *c2 = __dp4a(a2.z, b0.z, *c2); *c2 = __dp4a(a2.w, b0.w, *c2);
          *c3 = __dp4a(a3.x, b0.x, *c3); *c3 = __dp4a(a3.y, b0.y, *c3);
          *c3 = __dp4a(a3.z, b0.z, *c3); *c3 = __dp4a(a3.w, b0.w, *c3);
        }
      }
    }

    // epilogue (cols 72..127)
    #pragma unroll
    for (int i = 0; i < 4; i++) {
      const int r = m0 + rowbase + 16 * i;
      const float rxy = __fdiv_rn(sxp[r], syp[r]);
      float* o = out + (size_t)r * ND;
      #pragma unroll
      for (int j = 0; j < 7; j++) {
        const int c = n0 + 72 + tx + 8 * j;
        const float s = __fmul_rn(rxy, swp[c]);
        const float f = __fmul_rn(__int2float_rn(dacc[i][j]), s);
        int q = __float2int_rn(f);
        q = q < -128 ? -128 : (q > 127 ? 127 : q);
        o[c] = (float)q;
      }
    }
  }
}

} // namespace i8g

extern "C" void kernel_launch(void* const* d_in, const int* in_sizes, int n_in,
                              void* d_out, int out_size) {
  using namespace i8g;

  const void* x = nullptr; const void* w = nullptr;
  const float *sx = nullptr, *sw = nullptr, *sy = nullptr;
  for (int i = 0; i < n_in; i++) {
    const long long n = (long long)in_sizes[i];
    if (n == (long long)SD * KD)       x = d_in[i];
    else if (n == (long long)ND * KD)  w = d_in[i];
    else if (n == ND)                  sw = (const float*)d_in[i];
    else if (n == SD) { if (!sx) sx = (const float*)d_in[i]; else sy = (const float*)d_in[i]; }
  }
  if (!x || !w || !sx || !sw || !sy) return;

  float* out = (float*)d_out;

  {
    const int total = NX16 + NW16;
    pack_all_kernel<<<(total + 255) / 256, 256>>>((const uint4*)x, (const uint4*)w);
  }

  cudaFuncSetAttribute(i8gemm_kernel, cudaFuncAttributeMaxDynamicSharedMemorySize,
                       (int)SMEM_BYTES);
  dim3 grid(ND / BN, SD / BM);   // (32, 128)
  i8gemm_kernel<<<grid, THREADS, SMEM_BYTES>>>(sx, sw, sy, out);

  const size_t SN = (size_t)SD * (size_t)ND;
  if ((size_t)out_size > SN) {
    cudaMemcpyAsync((float*)d_out + SN, sy,
                    ((size_t)out_size - SN) * sizeof(float),
                    cudaMemcpyDeviceToDevice);
  }
}